// round 17
// baseline (speedup 1.0000x reference)
#include <cuda_runtime.h>
#include <cstddef>

// Pixel_RNNcontrol: h_t = tanh(x_t @ W_ih^T + h_{t-1} @ W_hh^T + b), out = sigmoid(10 h_t)
// T=128, B=262144, I=H=2. One thread handles 2 batch elements (float4 lanes).
//
// R17: R14 config (float4, PF=3, 256thr, .cg loads / .cs stores; best 88.2us /
// 83.8 ncu / DRAM 75.3%) with the unrolled group re-scheduled: batch all 3
// LDGs, then all 3 serial compute chains, then all 3 STGs back-to-back.
// Triples same-direction burst run-length per warp -> fewer DRAM read/write
// turnarounds. Costs 3 output regs (+12); launch_bounds(256,4) keeps 4 CTA/SM.

#define PF 3   // prefetch depth == group size

__device__ __forceinline__ float exact_tanh(float z) {
    // tanh(z) = 1 - 2/(1 + e^{2z}); z bounded (|z| <~ 7) -> no overflow
    float k = 2.885390082f * z;        // 2*log2(e) * z
    float e;
    asm("ex2.approx.f32 %0, %1;" : "=f"(e) : "f"(k));
    float r;
    float d = e + 1.0f;
    asm("rcp.approx.f32 %0, %1;" : "=f"(r) : "f"(d));
    return fmaf(-2.0f, r, 1.0f);
}

__device__ __forceinline__ float sig10(float h) {
    // sigmoid(10h) = 0.5 + 0.5*tanh(5h); HW tanh -> 1 MUFU, error non-accumulating
    float t;
    float a = 5.0f * h;
    asm("tanh.approx.f32 %0, %1;" : "=f"(t) : "f"(a));
    return fmaf(0.5f, t, 0.5f);
}

__global__ void __launch_bounds__(256, 4)
rnn_sigmoid_kernel(const float4* __restrict__ x4,
                   const float4* __restrict__ h04,
                   const float*  __restrict__ Wih,
                   const float*  __restrict__ Whh,
                   const float*  __restrict__ bih,
                   const float*  __restrict__ bhh,
                   float4* __restrict__ out4,
                   float4* __restrict__ hout4,
                   int T, int npairs)
{
    int p = blockIdx.x * blockDim.x + threadIdx.x;
    if (p >= npairs) return;

    // 2x2 weights (row-major). z = x @ W^T  ->  z0 = W[0][0]*x0 + W[0][1]*x1
    const float a00 = Wih[0], a01 = Wih[1], a10 = Wih[2], a11 = Wih[3];
    const float w00 = Whh[0], w01 = Whh[1], w10 = Whh[2], w11 = Whh[3];
    const float b0 = bih[0] + bhh[0];
    const float b1 = bih[1] + bhh[1];

    float4 hv = h04[p];
    float hA0 = hv.x, hA1 = hv.y;   // batch element A
    float hB0 = hv.z, hB1 = hv.w;   // batch element B

    // Prime the pipeline: PF loads in flight before the loop.
    float4 buf[PF];
    #pragma unroll
    for (int i = 0; i < PF; ++i) {
        int ti = (i < T) ? i : (T - 1);
        buf[i] = __ldcg(&x4[(size_t)ti * npairs + p]);
    }

    const float4* xld = x4 + (size_t)PF * npairs + p;   // next load addr (t = PF)
    float4*       ost = out4 + p;                        // store addr (t = 0)
    const size_t  stride = (size_t)npairs;

    int t = 0;

    // Main loop (t + 2*PF <= T): batch LDGs, then computes, then STGs.
    for (; t + 2 * PF <= T; t += PF) {
        float4 xv[PF], o[PF];

        // Phase 1: consume buffers, issue all PF prefetch LDGs back-to-back.
        #pragma unroll
        for (int i = 0; i < PF; ++i) {
            xv[i]  = buf[i];
            buf[i] = __ldcg(&xld[(size_t)i * stride]);
        }

        // Phase 2: serial recurrence for PF steps (no memory ops).
        #pragma unroll
        for (int i = 0; i < PF; ++i) {
            float zA0 = fmaf(a00, xv[i].x, fmaf(a01, xv[i].y, fmaf(w00, hA0, fmaf(w01, hA1, b0))));
            float zA1 = fmaf(a10, xv[i].x, fmaf(a11, xv[i].y, fmaf(w10, hA0, fmaf(w11, hA1, b1))));
            float zB0 = fmaf(a00, xv[i].z, fmaf(a01, xv[i].w, fmaf(w00, hB0, fmaf(w01, hB1, b0))));
            float zB1 = fmaf(a10, xv[i].z, fmaf(a11, xv[i].w, fmaf(w10, hB0, fmaf(w11, hB1, b1))));

            hA0 = exact_tanh(zA0);
            hA1 = exact_tanh(zA1);
            hB0 = exact_tanh(zB0);
            hB1 = exact_tanh(zB1);

            o[i].x = sig10(hA0);
            o[i].y = sig10(hA1);
            o[i].z = sig10(hB0);
            o[i].w = sig10(hB1);
        }

        // Phase 3: all PF STGs back-to-back.
        #pragma unroll
        for (int i = 0; i < PF; ++i) {
            __stcs(&ost[(size_t)i * stride], o[i]);
        }

        xld += (size_t)PF * stride;
        ost += (size_t)PF * stride;
    }

    // Cleanup groups: predicated loads (R14 structure).
    for (; t + PF <= T; t += PF) {
        #pragma unroll
        for (int i = 0; i < PF; ++i) {
            float4 xv = buf[i];
            if (t + i + PF < T) buf[i] = __ldcg(&xld[(size_t)i * stride]);

            float zA0 = fmaf(a00, xv.x, fmaf(a01, xv.y, fmaf(w00, hA0, fmaf(w01, hA1, b0))));
            float zA1 = fmaf(a10, xv.x, fmaf(a11, xv.y, fmaf(w10, hA0, fmaf(w11, hA1, b1))));
            float zB0 = fmaf(a00, xv.z, fmaf(a01, xv.w, fmaf(w00, hB0, fmaf(w01, hB1, b0))));
            float zB1 = fmaf(a10, xv.z, fmaf(a11, xv.w, fmaf(w10, hB0, fmaf(w11, hB1, b1))));

            hA0 = exact_tanh(zA0);
            hA1 = exact_tanh(zA1);
            hB0 = exact_tanh(zB0);
            hB1 = exact_tanh(zB1);

            float4 o;
            o.x = sig10(hA0);
            o.y = sig10(hA1);
            o.z = sig10(hB0);
            o.w = sig10(hB1);
            __stcs(&ost[(size_t)i * stride], o);
        }
        xld += (size_t)PF * stride;
        ost += (size_t)PF * stride;
    }

    // Scalar tail (T % PF != 0).
    for (int i = 0; t < T; ++t, ++i) {
        float4 xv = buf[i];
        float zA0 = fmaf(a00, xv.x, fmaf(a01, xv.y, fmaf(w00, hA0, fmaf(w01, hA1, b0))));
        float zA1 = fmaf(a10, xv.x, fmaf(a11, xv.y, fmaf(w10, hA0, fmaf(w11, hA1, b1))));
        float zB0 = fmaf(a00, xv.z, fmaf(a01, xv.w, fmaf(w00, hB0, fmaf(w01, hB1, b0))));
        float zB1 = fmaf(a10, xv.z, fmaf(a11, xv.w, fmaf(w10, hB0, fmaf(w11, hB1, b1))));
        hA0 = exact_tanh(zA0);
        hA1 = exact_tanh(zA1);
        hB0 = exact_tanh(zB0);
        hB1 = exact_tanh(zB1);
        float4 o;
        o.x = sig10(hA0); o.y = sig10(hA1); o.z = sig10(hB0); o.w = sig10(hB1);
        __stcs(&ost[(size_t)i * stride], o);
    }

    float4 hf;
    hf.x = hA0; hf.y = hA1; hf.z = hB0; hf.w = hB1;
    hout4[p] = hf;
}

extern "C" void kernel_launch(void* const* d_in, const int* in_sizes, int n_in,
                              void* d_out, int out_size)
{
    const float* x   = (const float*)d_in[0];   // (T, B, 2)
    const float* h0  = (const float*)d_in[1];   // (1, B, 2)
    const float* Wih = (const float*)d_in[2];   // (2, 2)
    const float* Whh = (const float*)d_in[3];   // (2, 2)
    const float* bih = (const float*)d_in[4];   // (2,)
    const float* bhh = (const float*)d_in[5];   // (2,)

    const int BH = in_sizes[1];                 // B * H = B * 2
    const int B  = BH / 2;
    const int T  = in_sizes[0] / BH;            // (T*B*2) / (B*2)

    float* out = (float*)d_out;                 // first T*B*2 elems: out
    float* hout = out + ((size_t)out_size - (size_t)BH);  // last B*2 elems: hidden

    const int npairs = B / 2;                   // float4 granularity (2 batch elems)
    const int threads = 256;
    const int blocks = (npairs + threads - 1) / threads;

    rnn_sigmoid_kernel<<<blocks, threads>>>(
        (const float4*)x, (const float4*)h0,
        Wih, Whh, bih, bhh,
        (float4*)out, (float4*)hout,
        T, npairs);
}